// round 12
// baseline (speedup 1.0000x reference)
#include <cuda_runtime.h>
#include <cuda_fp16.h>
#include <stdint.h>

// ---------------- problem constants ----------------
#define NTRAJ  4096
#define LSTEPS 128
#define IND    32      // input_dim
#define LAT    64      // latent_dim

#define M_CTA  16      // rows per CTA
#define NCTA   (NTRAJ / M_CTA)   // 256
#define NTHR   256     // 8 warps
#define NSTEP  (LSTEPS - 1)      // 127

// smem strides (in elements)
#define SY_STR 68      // fp32 state arrays [16][68]
#define A_STR  168     // fp16 yc/cc        [16][168]  (also holds prev_y in [0:64))
#define H_STR  520     // fp16 hidden       [16][520]
#define RED_SZ 2304    // fp32 K-split partial scratch

// ---------------- weight fragment buffer ----------------
// Each (n8,k16) tile = 32 lanes x uint4: (hi0, hi1, lo0, lo1) fp16x2 pairs,
// mma.sync m16n8k16 B layout (split-fp16: w = hi + lo).
// Layout per GEMM: [ntile][ktile][lane]
#define OFF_O1  0       // Wo1  K=64  N=256 -> 4096
#define OFF_O2  4096    // Wo2  K=256 N=64  -> 4096
#define OFF_UR1 8192    // [Wu1|Wr1] K=160 N=512 -> 20480
#define OFF_U2  28672   // Wu2  K=256 N=64  -> 4096
#define OFF_R2  32768   // Wr2  K=256 N=64  -> 4096
#define OFF_N1  36864   // Wn1  K=160 N=256 -> 10240
#define OFF_N2  47104   // Wn2  K=256 N=128 -> 8192
#define FRAG_TOTAL 55296

__device__ uint4 g_wfrag[FRAG_TOTAL];

// ---------------- prologue: pack weights into split hi/lo fragment layout ----------------
__global__ void prep_frags(const float* __restrict__ Wo1, const float* __restrict__ Wo2,
                           const float* __restrict__ Wu1, const float* __restrict__ Wu2,
                           const float* __restrict__ Wr1, const float* __restrict__ Wr2,
                           const float* __restrict__ Wn1, const float* __restrict__ Wn2) {
    int idx = blockIdx.x * blockDim.x + threadIdx.x;
    if (idx >= FRAG_TOTAL) return;
    int base, K, N;
    const float *W0, *W1 = nullptr;
    if (idx < OFF_O2)       { base = OFF_O1;  K = 64;  N = 256; W0 = Wo1; }
    else if (idx < OFF_UR1) { base = OFF_O2;  K = 256; N = 64;  W0 = Wo2; }
    else if (idx < OFF_U2)  { base = OFF_UR1; K = 160; N = 512; W0 = Wu1; W1 = Wr1; }
    else if (idx < OFF_R2)  { base = OFF_U2;  K = 256; N = 64;  W0 = Wu2; }
    else if (idx < OFF_N1)  { base = OFF_R2;  K = 256; N = 64;  W0 = Wr2; }
    else if (idx < OFF_N2)  { base = OFF_N1;  K = 160; N = 256; W0 = Wn1; }
    else                    { base = OFF_N2;  K = 256; N = 128; W0 = Wn2; }
    int li   = idx - base;
    int lane = li & 31;
    int tile = li >> 5;
    int KT   = K >> 4;
    int kt   = tile % KT, nt = tile / KT;
    int g    = lane >> 2, tq = lane & 3;
    int n    = nt * 8 + g;
    int k0   = kt * 16 + tq * 2;
    float v0, v1, v2, v3;
    if (W1) {  // concatenated [Wu1 | Wr1] along N, each source is [160,256]
        const float* S = (n < 256) ? W0 : W1;
        int nn = (n < 256) ? n : (n - 256);
        v0 = S[(k0    ) * 256 + nn]; v1 = S[(k0 + 1) * 256 + nn];
        v2 = S[(k0 + 8) * 256 + nn]; v3 = S[(k0 + 9) * 256 + nn];
    } else {
        v0 = W0[(k0    ) * N + n];   v1 = W0[(k0 + 1) * N + n];
        v2 = W0[(k0 + 8) * N + n];   v3 = W0[(k0 + 9) * N + n];
    }
    __half h0 = __float2half_rn(v0), h1 = __float2half_rn(v1);
    __half h2 = __float2half_rn(v2), h3 = __float2half_rn(v3);
    __half l0 = __float2half_rn(v0 - __half2float(h0));
    __half l1 = __float2half_rn(v1 - __half2float(h1));
    __half l2 = __float2half_rn(v2 - __half2float(h2));
    __half l3 = __float2half_rn(v3 - __half2float(h3));
    __half2 hh0 = __halves2half2(h0, h1), hh1 = __halves2half2(h2, h3);
    __half2 ll0 = __halves2half2(l0, l1), ll1 = __halves2half2(l2, l3);
    uint4 r;
    r.x = *reinterpret_cast<unsigned*>(&hh0);
    r.y = *reinterpret_cast<unsigned*>(&hh1);
    r.z = *reinterpret_cast<unsigned*>(&ll0);
    r.w = *reinterpret_cast<unsigned*>(&ll1);
    g_wfrag[idx] = r;
}

// ---------------- device helpers ----------------
__device__ __forceinline__ void mma16816(float* c, const unsigned* a, const unsigned* b) {
    asm volatile(
        "mma.sync.aligned.m16n8k16.row.col.f32.f16.f16.f32 "
        "{%0,%1,%2,%3}, {%4,%5,%6,%7}, {%8,%9}, {%0,%1,%2,%3};"
        : "+f"(c[0]), "+f"(c[1]), "+f"(c[2]), "+f"(c[3])
        : "r"(a[0]), "r"(a[1]), "r"(a[2]), "r"(a[3]), "r"(b[0]), "r"(b[1]));
}

__device__ __forceinline__ void ldsm4(unsigned* r, uint32_t addr) {
    asm volatile("ldmatrix.sync.aligned.m8n8.x4.shared.b16 {%0,%1,%2,%3}, [%4];"
                 : "=r"(r[0]), "=r"(r[1]), "=r"(r[2]), "=r"(r[3]) : "r"(addr));
}

__device__ __forceinline__ uint32_t smaddr(const void* p) {
    return (uint32_t)__cvta_generic_to_shared(p);
}

__device__ __forceinline__ float tanh_fast(float x) {
    float e = __expf(2.0f * x);
    return 1.0f - __fdividef(2.0f, e + 1.0f);
}
__device__ __forceinline__ float sigm_fast(float x) {
    return __fdividef(1.0f, 1.0f + __expf(-x));
}

// paired split store: two adjacent columns -> one half2 store per array (idx must be even)
__device__ __forceinline__ void st_split2(__half* hi, __half* lo, int idx, float v0, float v1) {
    __half h0 = __float2half_rn(v0), h1 = __float2half_rn(v1);
    *reinterpret_cast<__half2*>(hi + idx) = __halves2half2(h0, h1);
    *reinterpret_cast<__half2*>(lo + idx) = __halves2half2(
        __float2half_rn(v0 - __half2float(h0)),
        __float2half_rn(v1 - __half2float(h1)));
}

// Warp GEMM (split-fp16, 3 products), M=16: C[16, NT*8] = (Ah+Al)(Bh+Bl) approx.
// A via one ldmatrix.x4 per hi/lo per k-tile, B from fragment buffer (uint4 = hi|lo),
// PF-deep circular B prefetch. SPLIT: 3 independent accumulator banks.
// KSTRIDE (if nonzero): per-ntile k stride in the fragment buffer (for K-split
// calls where this call's KT < the stored KT). Caller must offset BOTH the
// fragment pointer (by k0*32) AND the A pointers (by k0*16 halfs).
template<int NT, int KT, int PF, bool SPLIT, int KSTRIDE = 0>
__device__ __forceinline__ void gemm3(float (&acc)[NT][4],
                                      const __half* __restrict__ sAh,
                                      const __half* __restrict__ sAl,
                                      const int strideA, const uint4* __restrict__ frag,
                                      const int nt0, const int lane) {
    constexpr int KS = KSTRIDE ? KSTRIDE : KT;
    float accQ[NT][4], accR[NT][4];
#pragma unroll
    for (int nt = 0; nt < NT; nt++)
#pragma unroll
        for (int i = 0; i < 4; i++) {
            acc[nt][i] = 0.0f;
            if (SPLIT) { accQ[nt][i] = 0.0f; accR[nt][i] = 0.0f; }
        }

    const int row_l = (lane & 7) + ((lane >> 3) & 1) * 8;
    const int colh  = ((lane >> 4) & 1) * 8;
    uint32_t aH = smaddr(sAh + row_l * strideA + colh);
    uint32_t aL = smaddr(sAl + row_l * strideA + colh);

    const uint4* fp = frag + (size_t)nt0 * KS * 32 + lane;

    uint4 b[PF][NT];
#pragma unroll
    for (int p = 0; p < PF; p++)
#pragma unroll
        for (int nt = 0; nt < NT; nt++) b[p][nt] = __ldg(fp + (nt * KS + p) * 32);

#pragma unroll
    for (int kt = 0; kt < KT; kt++) {
        const int cur = kt % PF;
        unsigned ah[4], al[4];
        const uint32_t off = kt * 32;   // 16 halfs = 32 bytes
        ldsm4(ah, aH + off);
        ldsm4(al, aL + off);

        if (SPLIT) {
#pragma unroll
            for (int nt = 0; nt < NT; nt++) {
                unsigned bh[2] = { b[cur][nt].x, b[cur][nt].y };
                mma16816(acc[nt],  ah, bh);
            }
#pragma unroll
            for (int nt = 0; nt < NT; nt++) {
                unsigned bl[2] = { b[cur][nt].z, b[cur][nt].w };
                mma16816(accQ[nt], ah, bl);
            }
#pragma unroll
            for (int nt = 0; nt < NT; nt++) {
                unsigned bh[2] = { b[cur][nt].x, b[cur][nt].y };
                mma16816(accR[nt], al, bh);
            }
        } else {
#pragma unroll
            for (int nt = 0; nt < NT; nt++) {
                unsigned bh[2] = { b[cur][nt].x, b[cur][nt].y };
                mma16816(acc[nt], ah, bh);
            }
#pragma unroll
            for (int nt = 0; nt < NT; nt++) {
                unsigned bl[2] = { b[cur][nt].z, b[cur][nt].w };
                mma16816(acc[nt], ah, bl);
            }
#pragma unroll
            for (int nt = 0; nt < NT; nt++) {
                unsigned bh[2] = { b[cur][nt].x, b[cur][nt].y };
                mma16816(acc[nt], al, bh);
            }
        }

        const int knext = kt + PF;
        if (knext < KT) {
#pragma unroll
            for (int nt = 0; nt < NT; nt++) b[cur][nt] = __ldg(fp + (nt * KS + knext) * 32);
        }
    }

    if (SPLIT) {
#pragma unroll
        for (int nt = 0; nt < NT; nt++)
#pragma unroll
            for (int i = 0; i < 4; i++)
                acc[nt][i] += accQ[nt][i] + accR[nt][i];
    }
}

// ---------------- main recurrent kernel ----------------
#define SMEM_F32   (4 * M_CTA * SY_STR + 1344 + 128 + RED_SZ)    // 8128 floats
#define SMEM_F16   (2 * M_CTA * (A_STR + H_STR))                 // 22016 halfs
#define SMEM_BYTES (SMEM_F32 * 4 + SMEM_F16 * 2)                 // 76544

__global__ void __launch_bounds__(NTHR, 2)
odernn_kernel(const float* __restrict__ data, const float* __restrict__ ts,
              const float* __restrict__ bo1, const float* __restrict__ bo2,
              const float* __restrict__ bu1, const float* __restrict__ bu2,
              const float* __restrict__ br1, const float* __restrict__ br2,
              const float* __restrict__ bn1, const float* __restrict__ bn2,
              float* __restrict__ out) {
    extern __shared__ unsigned char smraw[];
    float* s_y    = (float*)smraw;                 // [16][68] current y
    float* s_lv   = s_y  + M_CTA * SY_STR;         // [16][68] current logvar
    float* s_yo   = s_lv + M_CTA * SY_STR;         // [16][68] y_ode
    float* s_u    = s_yo + M_CTA * SY_STR;         // [16][68] update gate
    float* s_bias = s_u  + M_CTA * SY_STR;         // 1344
    float* s_dt   = s_bias + 1344;                 // 128
    float* s_red  = s_dt + 128;                    // 2304 K-split partials
    __half* s_ah  = (__half*)(s_red + RED_SZ);     // [16][168] prev_y/yc/cc hi
    __half* s_al  = s_ah  + M_CTA * A_STR;         //           lo
    __half* s_hh  = s_al  + M_CTA * A_STR;         // [16][520] hidden hi
    __half* s_hl  = s_hh  + M_CTA * H_STR;         //           lo

    const int tid  = threadIdx.x;
    const int lane = tid & 31;
    const int w    = tid >> 5;      // 0..7
    const int g    = lane >> 2;
    const int tq   = lane & 3;
    const int r0   = blockIdx.x * M_CTA;

    // ---- init ----
    for (int i = tid; i < M_CTA * SY_STR; i += NTHR) { s_y[i] = 0.f; s_lv[i] = 0.f; s_yo[i] = 0.f; s_u[i] = 0.f; }
    for (int i = tid; i < M_CTA * A_STR;  i += NTHR) { s_ah[i]  = __float2half(0.f); s_al[i]  = __float2half(0.f); }
    for (int i = tid; i < 256; i += NTHR) s_bias[i]        = bo1[i];
    for (int i = tid; i < 64;  i += NTHR) s_bias[256 + i]  = bo2[i];
    for (int i = tid; i < 256; i += NTHR) s_bias[320 + i]  = bu1[i];
    for (int i = tid; i < 64;  i += NTHR) s_bias[576 + i]  = bu2[i];
    for (int i = tid; i < 256; i += NTHR) s_bias[640 + i]  = br1[i];
    for (int i = tid; i < 64;  i += NTHR) s_bias[896 + i]  = br2[i];
    for (int i = tid; i < 256; i += NTHR) s_bias[960 + i]  = bn1[i];
    for (int i = tid; i < 128; i += NTHR) s_bias[1216 + i] = bn2[i];
    for (int i = tid; i < NSTEP; i += NTHR) s_dt[i] = (i == 0) ? (ts[1] - ts[0]) : (ts[i] - ts[i + 1]);
    // prologue: x_0 = data[:, 1, :] into s_a[128:160)
    if (tid < 128) {
        int row = tid >> 3, q = tid & 7;
        const float4* xp = (const float4*)(data + ((size_t)(r0 + row) * LSTEPS + 1) * IND);
        float4 v = __ldg(xp + q);
        int bidx = row * A_STR + 128 + q * 4;
        st_split2(s_ah, s_al, bidx + 0, v.x, v.y);
        st_split2(s_ah, s_al, bidx + 2, v.z, v.w);
    }
    __syncthreads();

    for (int j = 0; j < NSTEP; j++) {
        // ---- phase 1: G1: H_o = tanh(prev_y @ Wo1 + bo1), N=256, prev_y in s_a[0:64) ----
        {
            float acc[4][4];
            gemm3<4, 4, 2, false>(acc, s_ah, s_al, A_STR, g_wfrag + OFF_O1, w * 4, lane);
#pragma unroll
            for (int nt = 0; nt < 4; nt++)
#pragma unroll
                for (int ip = 0; ip < 4; ip += 2) {
                    int row = g + ((ip & 2) ? 8 : 0);
                    int col = w * 32 + nt * 8 + 2 * tq;
                    st_split2(s_hh, s_hl, row * H_STR + col,
                              tanh_fast(acc[nt][ip] + s_bias[col]),
                              tanh_fast(acc[nt][ip + 1] + s_bias[col + 1]));
                }
        }
        __syncthreads();

        // ---- phase 2 (K-split): warps 0-3 kt 0-7, warps 4-7 kt 8-15, NT=2 each.
        //      y_ode = prev_y + (H_o @ Wo2 + bo2) * dt, N=64 ----
        {
            const int khalf = w >> 2;
            const int kofs  = khalf * 128;   // 8 k-tiles x 16 halfs into the A row
            float acc[2][4];
            gemm3<2, 8, 8, true, 16>(acc, s_hh + kofs, s_hl + kofs, H_STR,
                                     g_wfrag + OFF_O2 + khalf * 8 * 32, (w & 3) * 2, lane);
            if (khalf) {   // store partial
#pragma unroll
                for (int nt = 0; nt < 2; nt++)
#pragma unroll
                    for (int ip = 0; ip < 4; ip += 2) {
                        int row = g + ((ip & 2) ? 8 : 0);
                        int col = (w & 3) * 16 + nt * 8 + 2 * tq;
                        *reinterpret_cast<float2*>(s_red + row * 68 + col) =
                            make_float2(acc[nt][ip], acc[nt][ip + 1]);
                    }
            }
            __syncthreads();
            if (!khalf) {
                float dt = s_dt[j];
#pragma unroll
                for (int nt = 0; nt < 2; nt++)
#pragma unroll
                    for (int ip = 0; ip < 4; ip += 2) {
                        int row = g + ((ip & 2) ? 8 : 0);
                        int col = w * 16 + nt * 8 + 2 * tq;
                        float2 p = *reinterpret_cast<float2*>(s_red + row * 68 + col);
                        float yo0 = s_y[row * SY_STR + col]     + (acc[nt][ip]     + p.x + s_bias[256 + col])     * dt;
                        float yo1 = s_y[row * SY_STR + col + 1] + (acc[nt][ip + 1] + p.y + s_bias[256 + col + 1]) * dt;
                        s_yo[row * SY_STR + col]     = yo0;
                        s_yo[row * SY_STR + col + 1] = yo1;
                        st_split2(s_ah, s_al, row * A_STR + col, yo0, yo1);
                    }
            }
        }
        __syncthreads();

        // ---- phase 3: G3: [HU|HR] = tanh(yc @ [Wu1|Wr1] + [bu1|br1]), N=512 ----
        {
#pragma unroll
            for (int c = 0; c < 2; c++) {
                float acc[4][4];
                gemm3<4, 10, 2, false>(acc, s_ah, s_al, A_STR, g_wfrag + OFF_UR1, w * 8 + c * 4, lane);
#pragma unroll
                for (int nt = 0; nt < 4; nt++)
#pragma unroll
                    for (int ip = 0; ip < 4; ip += 2) {
                        int row = g + ((ip & 2) ? 8 : 0);
                        int n = w * 64 + c * 32 + nt * 8 + 2 * tq;
                        float b0 = (n < 256) ? s_bias[320 + n] : s_bias[384 + n];
                        float b1 = (n + 1 < 256) ? s_bias[320 + n + 1] : s_bias[384 + n + 1];
                        st_split2(s_hh, s_hl, row * H_STR + n,
                                  tanh_fast(acc[nt][ip] + b0),
                                  tanh_fast(acc[nt][ip + 1] + b1));
                    }
            }
        }
        // P3->P4: warps 0-3 consume HU (written by warps 0-3); warps 4-7 consume HR.
        asm volatile("bar.sync %0, 128;" :: "r"(1 + (w >> 2)) : "memory");

        // ---- phase 4 (warp-paired + K-split): warps 0-3 U, warps 4-7 R.
        //      within each: (nhalf, khalf) = (w&1, (w>>1)&1); NT=4, KT=8 ----
        {
            const bool is_u = (w < 4);
            const int nhalf = w & 1;
            const int khalf = (w >> 1) & 1;
            const int kofs  = khalf * 128;
            const __half* bh = (is_u ? s_hh : (s_hh + 256)) + kofs;
            const __half* bl = (is_u ? s_hl : (s_hl + 256)) + kofs;
            const uint4* fr  = g_wfrag + (is_u ? OFF_U2 : OFF_R2) + khalf * 8 * 32;
            float acc[4][4];
            gemm3<4, 8, 4, false, 16>(acc, bh, bl, H_STR, fr, nhalf * 4, lane);
            float* red = s_red + (is_u ? 0 : 1152);
            if (khalf) {   // store partial
#pragma unroll
                for (int nt = 0; nt < 4; nt++)
#pragma unroll
                    for (int ip = 0; ip < 4; ip += 2) {
                        int row = g + ((ip & 2) ? 8 : 0);
                        int col = nhalf * 32 + nt * 8 + 2 * tq;
                        *reinterpret_cast<float2*>(red + row * 68 + col) =
                            make_float2(acc[nt][ip], acc[nt][ip + 1]);
                    }
            }
            asm volatile("bar.sync %0, 128;" :: "r"(1 + (w >> 2)) : "memory");
            if (!khalf) {
                if (is_u) {
#pragma unroll
                    for (int nt = 0; nt < 4; nt++)
#pragma unroll
                        for (int ip = 0; ip < 4; ip += 2) {
                            int row = g + ((ip & 2) ? 8 : 0);
                            int col = nhalf * 32 + nt * 8 + 2 * tq;
                            float2 p = *reinterpret_cast<float2*>(red + row * 68 + col);
                            s_u[row * SY_STR + col]     = sigm_fast(acc[nt][ip]     + p.x + s_bias[576 + col]);
                            s_u[row * SY_STR + col + 1] = sigm_fast(acc[nt][ip + 1] + p.y + s_bias[576 + col + 1]);
                        }
                } else {
#pragma unroll
                    for (int nt = 0; nt < 4; nt++)
#pragma unroll
                        for (int ip = 0; ip < 4; ip += 2) {
                            int row = g + ((ip & 2) ? 8 : 0);
                            int col = nhalf * 32 + nt * 8 + 2 * tq;
                            float2 p = *reinterpret_cast<float2*>(red + row * 68 + col);
                            float r0v = sigm_fast(acc[nt][ip]     + p.x + s_bias[896 + col]);
                            float r1v = sigm_fast(acc[nt][ip + 1] + p.y + s_bias[896 + col + 1]);
                            st_split2(s_ah, s_al, row * A_STR + col,
                                      s_yo[row * SY_STR + col] * r0v,  s_yo[row * SY_STR + col + 1] * r1v);
                            st_split2(s_ah, s_al, row * A_STR + 64 + col,
                                      s_lv[row * SY_STR + col] * r0v,  s_lv[row * SY_STR + col + 1] * r1v);
                        }
                }
            }
        }
        __syncthreads();

        // ---- phase 5: G5: H_n = tanh(cc @ Wn1 + bn1), N=256 ----
        // also issue next-step x load (consumed in phase 6) to hide L2 latency
        float4 xv;
        const bool xload = (tid < 128) && (j + 1 < NSTEP);
        if (xload) {
            int row = tid >> 3, q = tid & 7;
            const float4* xp = (const float4*)(data + ((size_t)(r0 + row) * LSTEPS + (j + 2)) * IND);
            xv = __ldg(xp + q);
        }
        {
            float acc[4][4];
            gemm3<4, 10, 2, false>(acc, s_ah, s_al, A_STR, g_wfrag + OFF_N1, w * 4, lane);
#pragma unroll
            for (int nt = 0; nt < 4; nt++)
#pragma unroll
                for (int ip = 0; ip < 4; ip += 2) {
                    int row = g + ((ip & 2) ? 8 : 0);
                    int n = w * 32 + nt * 8 + 2 * tq;
                    st_split2(s_hh, s_hl, row * H_STR + n,
                              tanh_fast(acc[nt][ip] + s_bias[960 + n]),
                              tanh_fast(acc[nt][ip + 1] + s_bias[960 + n + 1]));
                }
        }
        __syncthreads();

        // ---- phase 6 (K-split): warps 0-3 kt 0-7, warps 4-7 kt 8-15, NT=4.
        //      h = H_n @ Wn2 + bn2; state update, N=128; store x_{j+1} ----
        {
            if (xload) {
                int row = tid >> 3, q = tid & 7;
                int bidx = row * A_STR + 128 + q * 4;
                st_split2(s_ah, s_al, bidx + 0, xv.x, xv.y);
                st_split2(s_ah, s_al, bidx + 2, xv.z, xv.w);
            }
            const int khalf = w >> 2;
            const int kofs  = khalf * 128;
            float acc[4][4];
            gemm3<4, 8, 4, false, 16>(acc, s_hh + kofs, s_hl + kofs, H_STR,
                                      g_wfrag + OFF_N2 + khalf * 8 * 32, (w & 3) * 4, lane);
            if (khalf) {   // store partial, stride 132
#pragma unroll
                for (int nt = 0; nt < 4; nt++)
#pragma unroll
                    for (int ip = 0; ip < 4; ip += 2) {
                        int row = g + ((ip & 2) ? 8 : 0);
                        int col = (w & 3) * 32 + nt * 8 + 2 * tq;
                        *reinterpret_cast<float2*>(s_red + row * 132 + col) =
                            make_float2(acc[nt][ip], acc[nt][ip + 1]);
                    }
            }
            __syncthreads();
            if (!khalf) {
#pragma unroll
                for (int nt = 0; nt < 4; nt++)
#pragma unroll
                    for (int ip = 0; ip < 4; ip += 2) {
                        int row = g + ((ip & 2) ? 8 : 0);
                        int n = w * 32 + nt * 8 + 2 * tq;
                        float2 p = *reinterpret_cast<float2*>(s_red + row * 132 + n);
                        float h0 = acc[nt][ip]     + p.x + s_bias[1216 + n];
                        float h1 = acc[nt][ip + 1] + p.y + s_bias[1216 + n + 1];
                        if (n < LAT) {   // warp-uniform (warps 0-1)
                            float u0 = s_u[row * SY_STR + n], u1 = s_u[row * SY_STR + n + 1];
                            float ny0 = (1.0f - u0) * h0 + u0 * s_yo[row * SY_STR + n];
                            float ny1 = (1.0f - u1) * h1 + u1 * s_yo[row * SY_STR + n + 1];
                            s_y[row * SY_STR + n]     = ny0;
                            s_y[row * SY_STR + n + 1] = ny1;
                            st_split2(s_ah, s_al, row * A_STR + n, ny0, ny1);  // prev_y for next G1
                        } else {
                            int c = n - LAT;
                            float u0 = s_u[row * SY_STR + c], u1 = s_u[row * SY_STR + c + 1];
                            float nl0 = (1.0f - u0) * fabsf(h0) + u0 * s_lv[row * SY_STR + c];
                            float nl1 = (1.0f - u1) * fabsf(h1) + u1 * s_lv[row * SY_STR + c + 1];
                            s_lv[row * SY_STR + c]     = nl0;
                            s_lv[row * SY_STR + c + 1] = nl1;
                            st_split2(s_ah, s_al, row * A_STR + 64 + c, nl0, nl1);
                        }
                    }
            }
        }
        __syncthreads();
    }

    // ---- write outputs: [yi (4096x64), yi_logvar (4096x64)] ----
    for (int i = tid; i < M_CTA * LAT; i += NTHR) {
        int row = i >> 6, c = i & 63;
        out[(size_t)(r0 + row) * LAT + c] = s_y[row * SY_STR + c];
        out[(size_t)NTRAJ * LAT + (size_t)(r0 + row) * LAT + c] = s_lv[row * SY_STR + c];
    }
}

// ---------------- launch ----------------
extern "C" void kernel_launch(void* const* d_in, const int* in_sizes, int n_in,
                              void* d_out, int out_size) {
    const float* data = (const float*)d_in[0];
    const float* ts   = (const float*)d_in[1];
    const float* Wo1  = (const float*)d_in[2];
    const float* bo1  = (const float*)d_in[3];
    const float* Wo2  = (const float*)d_in[4];
    const float* bo2  = (const float*)d_in[5];
    const float* Wu1  = (const float*)d_in[6];
    const float* bu1  = (const float*)d_in[7];
    const float* Wu2  = (const float*)d_in[8];
    const float* bu2  = (const float*)d_in[9];
    const float* Wr1  = (const float*)d_in[10];
    const float* br1  = (const float*)d_in[11];
    const float* Wr2  = (const float*)d_in[12];
    const float* br2  = (const float*)d_in[13];
    const float* Wn1  = (const float*)d_in[14];
    const float* bn1  = (const float*)d_in[15];
    const float* Wn2  = (const float*)d_in[16];
    const float* bn2  = (const float*)d_in[17];

    prep_frags<<<(FRAG_TOTAL + 255) / 256, 256>>>(Wo1, Wo2, Wu1, Wu2, Wr1, Wr2, Wn1, Wn2);

    cudaFuncSetAttribute(odernn_kernel, cudaFuncAttributeMaxDynamicSharedMemorySize, SMEM_BYTES);
    odernn_kernel<<<NCTA, NTHR, SMEM_BYTES>>>(data, ts,
                                              bo1, bo2, bu1, bu2, br1, br2, bn1, bn2,
                                              (float*)d_out);
}

// round 13
// speedup vs baseline: 1.0755x; 1.0755x over previous
#include <cuda_runtime.h>
#include <cuda_fp16.h>
#include <stdint.h>

// ---------------- problem constants ----------------
#define NTRAJ  4096
#define LSTEPS 128
#define IND    32      // input_dim
#define LAT    64      // latent_dim

#define M_CTA  16      // rows per CTA
#define NCTA   (NTRAJ / M_CTA)   // 256
#define NTHR   256     // 8 warps
#define NSTEP  (LSTEPS - 1)      // 127

// smem strides (in elements)
#define SY_STR 68      // fp32 state arrays [16][68]
#define A_STR  168     // fp16 yc/cc        [16][168]  (also holds prev_y in [0:64))
#define H_STR  520     // fp16 hidden       [16][520]

// ---------------- weight fragment buffer ----------------
// Each (n8,k16) tile = 32 lanes x uint4: (hi0, hi1, lo0, lo1) fp16x2 pairs,
// mma.sync m16n8k16 B layout (split-fp16: w = hi + lo).
// Layout per GEMM: [ntile][ktile][lane]
#define OFF_O1  0       // Wo1  K=64  N=256 -> 4096
#define OFF_O2  4096    // Wo2  K=256 N=64  -> 4096
#define OFF_UR1 8192    // [Wu1|Wr1] K=160 N=512 -> 20480
#define OFF_U2  28672   // Wu2  K=256 N=64  -> 4096
#define OFF_R2  32768   // Wr2  K=256 N=64  -> 4096
#define OFF_N1  36864   // Wn1  K=160 N=256 -> 10240
#define OFF_N2  47104   // Wn2  K=256 N=128 -> 8192
#define FRAG_TOTAL 55296

__device__ uint4 g_wfrag[FRAG_TOTAL];

// ---------------- prologue: pack weights into split hi/lo fragment layout ----------------
__global__ void prep_frags(const float* __restrict__ Wo1, const float* __restrict__ Wo2,
                           const float* __restrict__ Wu1, const float* __restrict__ Wu2,
                           const float* __restrict__ Wr1, const float* __restrict__ Wr2,
                           const float* __restrict__ Wn1, const float* __restrict__ Wn2) {
    int idx = blockIdx.x * blockDim.x + threadIdx.x;
    if (idx >= FRAG_TOTAL) return;
    int base, K, N;
    const float *W0, *W1 = nullptr;
    if (idx < OFF_O2)       { base = OFF_O1;  K = 64;  N = 256; W0 = Wo1; }
    else if (idx < OFF_UR1) { base = OFF_O2;  K = 256; N = 64;  W0 = Wo2; }
    else if (idx < OFF_U2)  { base = OFF_UR1; K = 160; N = 512; W0 = Wu1; W1 = Wr1; }
    else if (idx < OFF_R2)  { base = OFF_U2;  K = 256; N = 64;  W0 = Wu2; }
    else if (idx < OFF_N1)  { base = OFF_R2;  K = 256; N = 64;  W0 = Wr2; }
    else if (idx < OFF_N2)  { base = OFF_N1;  K = 160; N = 256; W0 = Wn1; }
    else                    { base = OFF_N2;  K = 256; N = 128; W0 = Wn2; }
    int li   = idx - base;
    int lane = li & 31;
    int tile = li >> 5;
    int KT   = K >> 4;
    int kt   = tile % KT, nt = tile / KT;
    int g    = lane >> 2, tq = lane & 3;
    int n    = nt * 8 + g;
    int k0   = kt * 16 + tq * 2;
    float v0, v1, v2, v3;
    if (W1) {  // concatenated [Wu1 | Wr1] along N, each source is [160,256]
        const float* S = (n < 256) ? W0 : W1;
        int nn = (n < 256) ? n : (n - 256);
        v0 = S[(k0    ) * 256 + nn]; v1 = S[(k0 + 1) * 256 + nn];
        v2 = S[(k0 + 8) * 256 + nn]; v3 = S[(k0 + 9) * 256 + nn];
    } else {
        v0 = W0[(k0    ) * N + n];   v1 = W0[(k0 + 1) * N + n];
        v2 = W0[(k0 + 8) * N + n];   v3 = W0[(k0 + 9) * N + n];
    }
    __half h0 = __float2half_rn(v0), h1 = __float2half_rn(v1);
    __half h2 = __float2half_rn(v2), h3 = __float2half_rn(v3);
    __half l0 = __float2half_rn(v0 - __half2float(h0));
    __half l1 = __float2half_rn(v1 - __half2float(h1));
    __half l2 = __float2half_rn(v2 - __half2float(h2));
    __half l3 = __float2half_rn(v3 - __half2float(h3));
    __half2 hh0 = __halves2half2(h0, h1), hh1 = __halves2half2(h2, h3);
    __half2 ll0 = __halves2half2(l0, l1), ll1 = __halves2half2(l2, l3);
    uint4 r;
    r.x = *reinterpret_cast<unsigned*>(&hh0);
    r.y = *reinterpret_cast<unsigned*>(&hh1);
    r.z = *reinterpret_cast<unsigned*>(&ll0);
    r.w = *reinterpret_cast<unsigned*>(&ll1);
    g_wfrag[idx] = r;
}

// ---------------- device helpers ----------------
__device__ __forceinline__ void mma16816(float* c, const unsigned* a, const unsigned* b) {
    asm volatile(
        "mma.sync.aligned.m16n8k16.row.col.f32.f16.f16.f32 "
        "{%0,%1,%2,%3}, {%4,%5,%6,%7}, {%8,%9}, {%0,%1,%2,%3};"
        : "+f"(c[0]), "+f"(c[1]), "+f"(c[2]), "+f"(c[3])
        : "r"(a[0]), "r"(a[1]), "r"(a[2]), "r"(a[3]), "r"(b[0]), "r"(b[1]));
}

__device__ __forceinline__ void ldsm4(unsigned* r, uint32_t addr) {
    asm volatile("ldmatrix.sync.aligned.m8n8.x4.shared.b16 {%0,%1,%2,%3}, [%4];"
                 : "=r"(r[0]), "=r"(r[1]), "=r"(r[2]), "=r"(r[3]) : "r"(addr));
}

__device__ __forceinline__ uint32_t smaddr(const void* p) {
    return (uint32_t)__cvta_generic_to_shared(p);
}

__device__ __forceinline__ float tanh_fast(float x) {
    float e = __expf(2.0f * x);
    return 1.0f - __fdividef(2.0f, e + 1.0f);
}
__device__ __forceinline__ float sigm_fast(float x) {
    return __fdividef(1.0f, 1.0f + __expf(-x));
}

// paired split store: two adjacent columns -> one half2 store per array (idx must be even)
__device__ __forceinline__ void st_split2(__half* hi, __half* lo, int idx, float v0, float v1) {
    __half h0 = __float2half_rn(v0), h1 = __float2half_rn(v1);
    *reinterpret_cast<__half2*>(hi + idx) = __halves2half2(h0, h1);
    *reinterpret_cast<__half2*>(lo + idx) = __halves2half2(
        __float2half_rn(v0 - __half2float(h0)),
        __float2half_rn(v1 - __half2float(h1)));
}

// Prefetch the first k-tile of a gemm's B fragments (issued BEFORE the barrier
// that precedes the gemm, so the LDG latency overlaps epilogue + barrier wait).
// KS = stored per-ntile k stride of the fragment region.
template<int NT, int KS>
__device__ __forceinline__ void preB(uint4 (&pre)[NT], const uint4* __restrict__ frag,
                                     const int nt0, const int lane) {
    const uint4* fp = frag + (size_t)nt0 * KS * 32 + lane;
#pragma unroll
    for (int nt = 0; nt < NT; nt++) pre[nt] = __ldg(fp + (size_t)nt * KS * 32);
}

// Warp GEMM (split-fp16, 3 products), M=16: C[16, NT*8] = (Ah+Al)(Bh+Bl) approx.
// A via one ldmatrix.x4 per hi/lo per k-tile, B from fragment buffer (uint4 = hi|lo),
// PF-deep circular B prefetch. SPLIT: 3 independent accumulator banks.
// pre (optional): k-tile 0's B fragments, already in flight/registers.
template<int NT, int KT, int PF, bool SPLIT>
__device__ __forceinline__ void gemm3(float (&acc)[NT][4],
                                      const __half* __restrict__ sAh,
                                      const __half* __restrict__ sAl,
                                      const int strideA, const uint4* __restrict__ frag,
                                      const int nt0, const int lane,
                                      const uint4* pre = nullptr) {
    float accQ[NT][4], accR[NT][4];
#pragma unroll
    for (int nt = 0; nt < NT; nt++)
#pragma unroll
        for (int i = 0; i < 4; i++) {
            acc[nt][i] = 0.0f;
            if (SPLIT) { accQ[nt][i] = 0.0f; accR[nt][i] = 0.0f; }
        }

    const int row_l = (lane & 7) + ((lane >> 3) & 1) * 8;
    const int colh  = ((lane >> 4) & 1) * 8;
    uint32_t aH = smaddr(sAh + row_l * strideA + colh);
    uint32_t aL = smaddr(sAl + row_l * strideA + colh);

    const uint4* fp = frag + (size_t)nt0 * KT * 32 + lane;

    uint4 b[PF][NT];
    if (pre) {
#pragma unroll
        for (int nt = 0; nt < NT; nt++) b[0][nt] = pre[nt];
#pragma unroll
        for (int p = 1; p < PF; p++)
#pragma unroll
            for (int nt = 0; nt < NT; nt++) b[p][nt] = __ldg(fp + (nt * KT + p) * 32);
    } else {
#pragma unroll
        for (int p = 0; p < PF; p++)
#pragma unroll
            for (int nt = 0; nt < NT; nt++) b[p][nt] = __ldg(fp + (nt * KT + p) * 32);
    }

#pragma unroll
    for (int kt = 0; kt < KT; kt++) {
        const int cur = kt % PF;
        unsigned ah[4], al[4];
        const uint32_t off = kt * 32;   // 16 halfs = 32 bytes
        ldsm4(ah, aH + off);
        ldsm4(al, aL + off);

        if (SPLIT) {
#pragma unroll
            for (int nt = 0; nt < NT; nt++) {
                unsigned bh[2] = { b[cur][nt].x, b[cur][nt].y };
                mma16816(acc[nt],  ah, bh);
            }
#pragma unroll
            for (int nt = 0; nt < NT; nt++) {
                unsigned bl[2] = { b[cur][nt].z, b[cur][nt].w };
                mma16816(accQ[nt], ah, bl);
            }
#pragma unroll
            for (int nt = 0; nt < NT; nt++) {
                unsigned bh[2] = { b[cur][nt].x, b[cur][nt].y };
                mma16816(accR[nt], al, bh);
            }
        } else {
            // product-major ordering: same-acc dependency distance = NT
#pragma unroll
            for (int nt = 0; nt < NT; nt++) {
                unsigned bh[2] = { b[cur][nt].x, b[cur][nt].y };
                mma16816(acc[nt], ah, bh);
            }
#pragma unroll
            for (int nt = 0; nt < NT; nt++) {
                unsigned bl[2] = { b[cur][nt].z, b[cur][nt].w };
                mma16816(acc[nt], ah, bl);
            }
#pragma unroll
            for (int nt = 0; nt < NT; nt++) {
                unsigned bh[2] = { b[cur][nt].x, b[cur][nt].y };
                mma16816(acc[nt], al, bh);
            }
        }

        const int knext = kt + PF;
        if (knext < KT) {
#pragma unroll
            for (int nt = 0; nt < NT; nt++) b[cur][nt] = __ldg(fp + (nt * KT + knext) * 32);
        }
    }

    if (SPLIT) {
#pragma unroll
        for (int nt = 0; nt < NT; nt++)
#pragma unroll
            for (int i = 0; i < 4; i++)
                acc[nt][i] += accQ[nt][i] + accR[nt][i];
    }
}

// ---------------- main recurrent kernel ----------------
// fp32: s_y, s_lv, s_yo, s_u (4x16x68), bias 1344, dt 128
// fp16: s_a (16x168 hi/lo; [0:64) doubles as prev_y), s_h (16x520 hi/lo)
#define SMEM_F32   (4 * M_CTA * SY_STR + 1344 + 128)             // 5824 floats
#define SMEM_F16   (2 * M_CTA * (A_STR + H_STR))                 // 22016 halfs
#define SMEM_BYTES (SMEM_F32 * 4 + SMEM_F16 * 2)                 // 67328

__global__ void __launch_bounds__(NTHR, 2)
odernn_kernel(const float* __restrict__ data, const float* __restrict__ ts,
              const float* __restrict__ bo1, const float* __restrict__ bo2,
              const float* __restrict__ bu1, const float* __restrict__ bu2,
              const float* __restrict__ br1, const float* __restrict__ br2,
              const float* __restrict__ bn1, const float* __restrict__ bn2,
              float* __restrict__ out) {
    extern __shared__ unsigned char smraw[];
    float* s_y    = (float*)smraw;                 // [16][68] current y
    float* s_lv   = s_y  + M_CTA * SY_STR;         // [16][68] current logvar
    float* s_yo   = s_lv + M_CTA * SY_STR;         // [16][68] y_ode
    float* s_u    = s_yo + M_CTA * SY_STR;         // [16][68] update gate
    float* s_bias = s_u  + M_CTA * SY_STR;         // 1344
    float* s_dt   = s_bias + 1344;                 // 128
    __half* s_ah  = (__half*)(s_dt + 128);         // [16][168] prev_y/yc/cc hi
    __half* s_al  = s_ah  + M_CTA * A_STR;         //           lo
    __half* s_hh  = s_al  + M_CTA * A_STR;         // [16][520] hidden hi
    __half* s_hl  = s_hh  + M_CTA * H_STR;         //           lo

    const int tid  = threadIdx.x;
    const int lane = tid & 31;
    const int w    = tid >> 5;      // 0..7
    const int g    = lane >> 2;
    const int tq   = lane & 3;
    const int r0   = blockIdx.x * M_CTA;

    // ---- init ----
    for (int i = tid; i < M_CTA * SY_STR; i += NTHR) { s_y[i] = 0.f; s_lv[i] = 0.f; s_yo[i] = 0.f; s_u[i] = 0.f; }
    for (int i = tid; i < M_CTA * A_STR;  i += NTHR) { s_ah[i]  = __float2half(0.f); s_al[i]  = __float2half(0.f); }
    for (int i = tid; i < 256; i += NTHR) s_bias[i]        = bo1[i];
    for (int i = tid; i < 64;  i += NTHR) s_bias[256 + i]  = bo2[i];
    for (int i = tid; i < 256; i += NTHR) s_bias[320 + i]  = bu1[i];
    for (int i = tid; i < 64;  i += NTHR) s_bias[576 + i]  = bu2[i];
    for (int i = tid; i < 256; i += NTHR) s_bias[640 + i]  = br1[i];
    for (int i = tid; i < 64;  i += NTHR) s_bias[896 + i]  = br2[i];
    for (int i = tid; i < 256; i += NTHR) s_bias[960 + i]  = bn1[i];
    for (int i = tid; i < 128; i += NTHR) s_bias[1216 + i] = bn2[i];
    for (int i = tid; i < NSTEP; i += NTHR) s_dt[i] = (i == 0) ? (ts[1] - ts[0]) : (ts[i] - ts[i + 1]);
    // prologue: x_0 = data[:, 1, :] into s_a[128:160)
    if (tid < 128) {
        int row = tid >> 3, q = tid & 7;
        const float4* xp = (const float4*)(data + ((size_t)(r0 + row) * LSTEPS + 1) * IND);
        float4 v = __ldg(xp + q);
        int bidx = row * A_STR + 128 + q * 4;
        st_split2(s_ah, s_al, bidx + 0, v.x, v.y);
        st_split2(s_ah, s_al, bidx + 2, v.z, v.w);
    }
    // prefetch G1's first B k-tile for step 0
    uint4 pre1[4];
    preB<4, 4>(pre1, g_wfrag + OFF_O1, w * 4, lane);
    __syncthreads();

    for (int j = 0; j < NSTEP; j++) {
        // ---- phase 1: G1: H_o = tanh(prev_y @ Wo1 + bo1), N=256, prev_y in s_a[0:64) ----
        {
            float acc[4][4];
            gemm3<4, 4, 2, false>(acc, s_ah, s_al, A_STR, g_wfrag + OFF_O1, w * 4, lane, pre1);
#pragma unroll
            for (int nt = 0; nt < 4; nt++)
#pragma unroll
                for (int ip = 0; ip < 4; ip += 2) {
                    int row = g + ((ip & 2) ? 8 : 0);
                    int col = w * 32 + nt * 8 + 2 * tq;
                    st_split2(s_hh, s_hl, row * H_STR + col,
                              tanh_fast(acc[nt][ip] + s_bias[col]),
                              tanh_fast(acc[nt][ip + 1] + s_bias[col + 1]));
                }
        }
        uint4 pre2[1];
        preB<1, 16>(pre2, g_wfrag + OFF_O2, w, lane);
        __syncthreads();

        // ---- phase 2: G2: y_ode = prev_y + (H_o @ Wo2 + bo2) * dt, N=64 ----
        {
            float acc[1][4];
            gemm3<1, 16, 8, true>(acc, s_hh, s_hl, H_STR, g_wfrag + OFF_O2, w, lane, pre2);
            float dt = s_dt[j];
#pragma unroll
            for (int ip = 0; ip < 4; ip += 2) {
                int row = g + ((ip & 2) ? 8 : 0);
                int col = w * 8 + 2 * tq;
                float yo0 = s_y[row * SY_STR + col]     + (acc[0][ip]     + s_bias[256 + col])     * dt;
                float yo1 = s_y[row * SY_STR + col + 1] + (acc[0][ip + 1] + s_bias[256 + col + 1]) * dt;
                s_yo[row * SY_STR + col]     = yo0;
                s_yo[row * SY_STR + col + 1] = yo1;
                st_split2(s_ah, s_al, row * A_STR + col, yo0, yo1);
            }
        }
        uint4 pre3[4];
        preB<4, 10>(pre3, g_wfrag + OFF_UR1, w * 8, lane);
        __syncthreads();

        // ---- phase 3: G3: [HU|HR] = tanh(yc @ [Wu1|Wr1] + [bu1|br1]), N=512 ----
        {
#pragma unroll
            for (int c = 0; c < 2; c++) {
                float acc[4][4];
                gemm3<4, 10, 2, false>(acc, s_ah, s_al, A_STR, g_wfrag + OFF_UR1,
                                       w * 8 + c * 4, lane, c == 0 ? pre3 : nullptr);
#pragma unroll
                for (int nt = 0; nt < 4; nt++)
#pragma unroll
                    for (int ip = 0; ip < 4; ip += 2) {
                        int row = g + ((ip & 2) ? 8 : 0);
                        int n = w * 64 + c * 32 + nt * 8 + 2 * tq;
                        float b0 = (n < 256) ? s_bias[320 + n] : s_bias[384 + n];
                        float b1 = (n + 1 < 256) ? s_bias[320 + n + 1] : s_bias[384 + n + 1];
                        st_split2(s_hh, s_hl, row * H_STR + n,
                                  tanh_fast(acc[nt][ip] + b0),
                                  tanh_fast(acc[nt][ip + 1] + b1));
                    }
            }
        }
        // P4 setup + B prefetch before the half-block barrier
        const bool is_u = (w < 4);
        const uint4* fr4 = g_wfrag + (is_u ? OFF_U2 : OFF_R2);
        const int nt04   = (w & 3) * 2;
        uint4 pre4[2];
        preB<2, 16>(pre4, fr4, nt04, lane);
        // P3->P4: warps 0-3 consume HU (written by warps 0-3); warps 4-7 consume HR.
        asm volatile("bar.sync %0, 128;" :: "r"(1 + (w >> 2)) : "memory");

        // ---- phase 4 (warp-paired): warps 0-3: u = sigmoid(HU @ Wu2 + bu2)
        //                             warps 4-7: r = sigmoid(HR @ Wr2 + br2); build cc ----
        {
            const __half* bh = is_u ? s_hh : (s_hh + 256);
            const __half* bl = is_u ? s_hl : (s_hl + 256);
            float acc[2][4];
            gemm3<2, 16, 4, true>(acc, bh, bl, H_STR, fr4, nt04, lane, pre4);
            if (is_u) {
#pragma unroll
                for (int nt = 0; nt < 2; nt++)
#pragma unroll
                    for (int i = 0; i < 4; i++) {
                        int row = g + ((i & 2) ? 8 : 0);
                        int col = (w & 3) * 16 + nt * 8 + 2 * tq + (i & 1);
                        s_u[row * SY_STR + col] = sigm_fast(acc[nt][i] + s_bias[576 + col]);
                    }
            } else {
#pragma unroll
                for (int nt = 0; nt < 2; nt++)
#pragma unroll
                    for (int ip = 0; ip < 4; ip += 2) {
                        int row = g + ((ip & 2) ? 8 : 0);
                        int col = (w & 3) * 16 + nt * 8 + 2 * tq;
                        float r0v = sigm_fast(acc[nt][ip]     + s_bias[896 + col]);
                        float r1v = sigm_fast(acc[nt][ip + 1] + s_bias[896 + col + 1]);
                        st_split2(s_ah, s_al, row * A_STR + col,
                                  s_yo[row * SY_STR + col] * r0v,  s_yo[row * SY_STR + col + 1] * r1v);
                        st_split2(s_ah, s_al, row * A_STR + 64 + col,
                                  s_lv[row * SY_STR + col] * r0v,  s_lv[row * SY_STR + col + 1] * r1v);
                    }
            }
        }
        uint4 pre5[4];
        preB<4, 10>(pre5, g_wfrag + OFF_N1, w * 4, lane);
        __syncthreads();

        // ---- phase 5: G5: H_n = tanh(cc @ Wn1 + bn1), N=256 ----
        // also issue next-step x load (consumed in phase 6) to hide L2 latency
        float4 xv;
        const bool xload = (tid < 128) && (j + 1 < NSTEP);
        if (xload) {
            int row = tid >> 3, q = tid & 7;
            const float4* xp = (const float4*)(data + ((size_t)(r0 + row) * LSTEPS + (j + 2)) * IND);
            xv = __ldg(xp + q);
        }
        {
            float acc[4][4];
            gemm3<4, 10, 2, false>(acc, s_ah, s_al, A_STR, g_wfrag + OFF_N1, w * 4, lane, pre5);
#pragma unroll
            for (int nt = 0; nt < 4; nt++)
#pragma unroll
                for (int ip = 0; ip < 4; ip += 2) {
                    int row = g + ((ip & 2) ? 8 : 0);
                    int n = w * 32 + nt * 8 + 2 * tq;
                    st_split2(s_hh, s_hl, row * H_STR + n,
                              tanh_fast(acc[nt][ip] + s_bias[960 + n]),
                              tanh_fast(acc[nt][ip + 1] + s_bias[960 + n + 1]));
                }
        }
        uint4 pre6[2];
        preB<2, 16>(pre6, g_wfrag + OFF_N2, w * 2, lane);
        __syncthreads();

        // ---- phase 6: h = H_n @ Wn2 + bn2; state update, N=128; store x_{j+1} ----
        {
            if (xload) {
                int row = tid >> 3, q = tid & 7;
                int bidx = row * A_STR + 128 + q * 4;
                st_split2(s_ah, s_al, bidx + 0, xv.x, xv.y);
                st_split2(s_ah, s_al, bidx + 2, xv.z, xv.w);
            }
            float acc[2][4];
            gemm3<2, 16, 4, true>(acc, s_hh, s_hl, H_STR, g_wfrag + OFF_N2, w * 2, lane, pre6);
#pragma unroll
            for (int nt = 0; nt < 2; nt++)
#pragma unroll
                for (int ip = 0; ip < 4; ip += 2) {
                    int row = g + ((ip & 2) ? 8 : 0);
                    int n = w * 16 + nt * 8 + 2 * tq;
                    float h0 = acc[nt][ip]     + s_bias[1216 + n];
                    float h1 = acc[nt][ip + 1] + s_bias[1216 + n + 1];
                    if (n < LAT) {   // warp-uniform (warps 0-3)
                        float u0 = s_u[row * SY_STR + n], u1 = s_u[row * SY_STR + n + 1];
                        float ny0 = (1.0f - u0) * h0 + u0 * s_yo[row * SY_STR + n];
                        float ny1 = (1.0f - u1) * h1 + u1 * s_yo[row * SY_STR + n + 1];
                        s_y[row * SY_STR + n]     = ny0;
                        s_y[row * SY_STR + n + 1] = ny1;
                        st_split2(s_ah, s_al, row * A_STR + n, ny0, ny1);  // prev_y for next G1
                    } else {
                        int c = n - LAT;
                        float u0 = s_u[row * SY_STR + c], u1 = s_u[row * SY_STR + c + 1];
                        float nl0 = (1.0f - u0) * fabsf(h0) + u0 * s_lv[row * SY_STR + c];
                        float nl1 = (1.0f - u1) * fabsf(h1) + u1 * s_lv[row * SY_STR + c + 1];
                        s_lv[row * SY_STR + c]     = nl0;
                        s_lv[row * SY_STR + c + 1] = nl1;
                        st_split2(s_ah, s_al, row * A_STR + 64 + c, nl0, nl1);
                    }
                }
        }
        preB<4, 4>(pre1, g_wfrag + OFF_O1, w * 4, lane);   // refresh G1 prefetch for next step
        __syncthreads();
    }

    // ---- write outputs: [yi (4096x64), yi_logvar (4096x64)] ----
    for (int i = tid; i < M_CTA * LAT; i += NTHR) {
        int row = i >> 6, c = i & 63;
        out[(size_t)(r0 + row) * LAT + c] = s_y[row * SY_STR + c];
        out[(size_t)NTRAJ * LAT + (size_t)(r0 + row) * LAT + c] = s_lv[row * SY_STR + c];
    }
}

// ---------------- launch ----------------
extern "C" void kernel_launch(void* const* d_in, const int* in_sizes, int n_in,
                              void* d_out, int out_size) {
    const float* data = (const float*)d_in[0];
    const float* ts   = (const float*)d_in[1];
    const float* Wo1  = (const float*)d_in[2];
    const float* bo1  = (const float*)d_in[3];
    const float* Wo2  = (const float*)d_in[4];
    const float* bo2  = (const float*)d_in[5];
    const float* Wu1  = (const float*)d_in[6];
    const float* bu1  = (const float*)d_in[7];
    const float* Wu2  = (const float*)d_in[8];
    const float* bu2  = (const float*)d_in[9];
    const float* Wr1  = (const float*)d_in[10];
    const float* br1  = (const float*)d_in[11];
    const float* Wr2  = (const float*)d_in[12];
    const float* br2  = (const float*)d_in[13];
    const float* Wn1  = (const float*)d_in[14];
    const float* bn1  = (const float*)d_in[15];
    const float* Wn2  = (const float*)d_in[16];
    const float* bn2  = (const float*)d_in[17];

    prep_frags<<<(FRAG_TOTAL + 255) / 256, 256>>>(Wo1, Wo2, Wu1, Wu2, Wr1, Wr2, Wn1, Wn2);

    cudaFuncSetAttribute(odernn_kernel, cudaFuncAttributeMaxDynamicSharedMemorySize, SMEM_BYTES);
    odernn_kernel<<<NCTA, NTHR, SMEM_BYTES>>>(data, ts,
                                              bo1, bo2, bu1, bu2, br1, br2, bn1, bn2,
                                              (float*)d_out);
}